// round 1
// baseline (speedup 1.0000x reference)
#include <cuda_runtime.h>
#include <cstdint>

#define TT 16384
#define DD 2048
#define EE 64
#define BM 128
#define BK 32
#define NTILE (DD / BK)          // 64
#define NTHREADS 256
#define XS_STRIDE (BM + 2)       // 130: odd*2 -> conflict-free LDS.64, keeps 8B alignment

// ---- shared memory layout (floats) ----
#define XS_BUF_FLOATS (BK * XS_STRIDE)                  // 4160
#define WS_OFF_FLOATS (2 * XS_BUF_FLOATS)               // 8320
#define WS_BUF_FLOATS (BK * EE)                         // 2048
#define TILES_FLOATS (WS_OFF_FLOATS + 2 * WS_BUF_FLOATS) // 12416
#define SC_STRIDE (EE + 1)                              // 65 (conflict-free column scans)
#define AUX_OFF_FLOATS TILES_FLOATS
// aux: counts[64] + i1[128] + i2[128] + g1[128] + g2[128] = 576 words
#define SMEM_FLOATS (AUX_OFF_FLOATS + 576)
#define SMEM_BYTES (SMEM_FLOATS * 4)                    // 51968 B

// output layout (floats), when all four outputs are concatenated
#define IDX_OFF  ((size_t)TT * EE)            // 1048576
#define GATE_OFF (IDX_OFF + 2 * (size_t)TT)   // 1081344
#define ACT_OFF  (GATE_OFF + 2 * (size_t)TT)  // 1114112
#define FULL_OUT (ACT_OFF + EE)               // 1114176

__device__ __forceinline__ void fma2(unsigned long long& d,
                                     unsigned long long a,
                                     unsigned long long b) {
    asm volatile("fma.rn.f32x2 %0, %1, %2, %0;" : "+l"(d) : "l"(a), "l"(b));
}

__device__ __forceinline__ unsigned long long bcast2(float x) {
    unsigned long long r;
    asm("mov.b64 %0, {%1, %1};" : "=l"(r) : "f"(x));
    return r;
}

__global__ void zero_act_kernel(float* __restrict__ act) {
    if (threadIdx.x < EE) act[threadIdx.x] = 0.0f;
}

__global__ __launch_bounds__(NTHREADS, 1)
void router_kernel(const float* __restrict__ x,
                   const float* __restrict__ w,
                   const float* __restrict__ noise,
                   float* __restrict__ out,
                   int write_extras) {
    extern __shared__ float sm[];
    float* xs = sm;                       // [2][BK][XS_STRIDE], transposed: [k][row]
    float* ws = sm + WS_OFF_FLOATS;       // [2][BK][EE]

    const int tid  = threadIdx.x;
    const int row0 = blockIdx.x * BM;
    const int rg   = tid & 63;            // row group: rows 2*rg, 2*rg+1
    const int cg   = tid >> 6;            // col group: cols 16*cg .. 16*cg+15

    unsigned long long acc[2][8];
#pragma unroll
    for (int r = 0; r < 2; r++)
#pragma unroll
        for (int c = 0; c < 8; c++) acc[r][c] = 0ull;

    // ---- preload tile 0 ----
    {
#pragma unroll
        for (int j = 0; j < 4; j++) {
            int chunk = tid + NTHREADS * j;         // 1024 float4 chunks of x tile
            int r = chunk >> 3, kc = chunk & 7;
            float4 v = *(const float4*)(x + (size_t)(row0 + r) * DD + kc * 4);
            xs[(kc * 4 + 0) * XS_STRIDE + r] = v.x;
            xs[(kc * 4 + 1) * XS_STRIDE + r] = v.y;
            xs[(kc * 4 + 2) * XS_STRIDE + r] = v.z;
            xs[(kc * 4 + 3) * XS_STRIDE + r] = v.w;
        }
#pragma unroll
        for (int j = 0; j < 2; j++) {
            int chunk = tid + NTHREADS * j;         // 512 float4 chunks of w tile
            int k = chunk >> 4, e4 = chunk & 15;
            float4 v = *(const float4*)(w + (size_t)k * EE + e4 * 4);
            *(float4*)(ws + k * EE + e4 * 4) = v;
        }
    }
    __syncthreads();

    int buf = 0;
    for (int kt = 0; kt < NTILE; ++kt) {
        float4 xr[4];
        float4 wr[2];
        const bool more = (kt + 1 < NTILE);
        if (more) {
            const int kbase = (kt + 1) * BK;
#pragma unroll
            for (int j = 0; j < 4; j++) {
                int chunk = tid + NTHREADS * j;
                int r = chunk >> 3, kc = chunk & 7;
                xr[j] = *(const float4*)(x + (size_t)(row0 + r) * DD + kbase + kc * 4);
            }
#pragma unroll
            for (int j = 0; j < 2; j++) {
                int chunk = tid + NTHREADS * j;
                int k = chunk >> 4, e4 = chunk & 15;
                wr[j] = *(const float4*)(w + (size_t)(kbase + k) * EE + e4 * 4);
            }
        }

        const float* xb = xs + buf * XS_BUF_FLOATS;
        const float* wb = ws + buf * WS_BUF_FLOATS;
#pragma unroll
        for (int k = 0; k < BK; k++) {
            float2 xv = *(const float2*)(xb + k * XS_STRIDE + 2 * rg);
            unsigned long long x0 = bcast2(xv.x);
            unsigned long long x1 = bcast2(xv.y);
            const ulonglong2* wp = (const ulonglong2*)(wb + k * EE + cg * 16);
            ulonglong2 wa = wp[0], wb2 = wp[1], wc = wp[2], wd = wp[3];
            fma2(acc[0][0], x0, wa.x);  fma2(acc[1][0], x1, wa.x);
            fma2(acc[0][1], x0, wa.y);  fma2(acc[1][1], x1, wa.y);
            fma2(acc[0][2], x0, wb2.x); fma2(acc[1][2], x1, wb2.x);
            fma2(acc[0][3], x0, wb2.y); fma2(acc[1][3], x1, wb2.y);
            fma2(acc[0][4], x0, wc.x);  fma2(acc[1][4], x1, wc.x);
            fma2(acc[0][5], x0, wc.y);  fma2(acc[1][5], x1, wc.y);
            fma2(acc[0][6], x0, wd.x);  fma2(acc[1][6], x1, wd.x);
            fma2(acc[0][7], x0, wd.y);  fma2(acc[1][7], x1, wd.y);
        }

        if (more) {
            __syncthreads();
            const int nb = buf ^ 1;
            float* xd = xs + nb * XS_BUF_FLOATS;
            float* wd = ws + nb * WS_BUF_FLOATS;
#pragma unroll
            for (int j = 0; j < 4; j++) {
                int chunk = tid + NTHREADS * j;
                int r = chunk >> 3, kc = chunk & 7;
                xd[(kc * 4 + 0) * XS_STRIDE + r] = xr[j].x;
                xd[(kc * 4 + 1) * XS_STRIDE + r] = xr[j].y;
                xd[(kc * 4 + 2) * XS_STRIDE + r] = xr[j].z;
                xd[(kc * 4 + 3) * XS_STRIDE + r] = xr[j].w;
            }
#pragma unroll
            for (int j = 0; j < 2; j++) {
                int chunk = tid + NTHREADS * j;
                int k = chunk >> 4, e4 = chunk & 15;
                *(float4*)(wd + k * EE + e4 * 4) = wr[j];
            }
            __syncthreads();
            buf = nb;
        }
    }

    // ================= epilogue =================
    __syncthreads();   // all done reading tiles; reuse smem as score board
    float* sc = sm;                                  // [BM][SC_STRIDE]
    int*   counts = (int*)(sm + AUX_OFF_FLOATS);     // [64]
    int*   i1a = counts + 64;                        // [128]
    int*   i2a = i1a + BM;                           // [128]
    float* g1a = (float*)(i2a + BM);                 // [128]
    float* g2a = g1a + BM;                           // [128]

    // scatter accumulators to the score board
#pragma unroll
    for (int r = 0; r < 2; r++) {
        int row = 2 * rg + r;
#pragma unroll
        for (int c = 0; c < 8; c++) {
            unsigned long long a = acc[r][c];
            float lo = __uint_as_float((unsigned)(a & 0xffffffffu));
            float hi = __uint_as_float((unsigned)(a >> 32));
            sc[row * SC_STRIDE + cg * 16 + 2 * c]     = lo;
            sc[row * SC_STRIDE + cg * 16 + 2 * c + 1] = hi;
        }
    }
    if (tid < EE) counts[tid] = 0;
    __syncthreads();

    // add noise (coalesced global reads)
#pragma unroll
    for (int j = 0; j < 32; j++) {
        int flat = tid + NTHREADS * j;               // 8192 elems
        int r = flat >> 6, e = flat & 63;
        sc[r * SC_STRIDE + e] += noise[(size_t)row0 * EE + flat];
    }
    __syncthreads();

    // per-row top-2 + gates (softmax is monotone; renormalized top-2 of softmax
    // == sigmoid of score difference)
    if (tid < BM) {
        const int row = tid;
        const float* p = sc + row * SC_STRIDE;
        float m1 = -3.402823466e38f, m2 = -3.402823466e38f;
        int b1 = 0, b2 = 0;
#pragma unroll
        for (int e = 0; e < EE; e++) {
            float z = p[e];
            if (z > m1) { m2 = m1; b2 = b1; m1 = z; b1 = e; }
            else if (z > m2) { m2 = z; b2 = e; }
        }
        float e2 = __expf(m2 - m1);
        float inv = 1.0f / (1.0f + e2);
        float g1 = inv, g2 = e2 * inv;
        i1a[row] = b1; i2a[row] = b2; g1a[row] = g1; g2a[row] = g2;
        atomicAdd(&counts[b1], 1);
        atomicAdd(&counts[b2], 1);
        if (write_extras) {
            float2 iv; iv.x = (float)b1; iv.y = (float)b2;
            *(float2*)(out + IDX_OFF + (size_t)(row0 + row) * 2) = iv;
            float2 gv; gv.x = g1; gv.y = g2;
            *(float2*)(out + GATE_OFF + (size_t)(row0 + row) * 2) = gv;
        }
    }
    __syncthreads();

    // combine tensor: full [BM][64] rows (zeros elsewhere), float4 coalesced
#pragma unroll
    for (int j = 0; j < 8; j++) {
        int chunk = tid + NTHREADS * j;              // 2048 float4 chunks
        int r = chunk >> 4, c4 = chunk & 15;
        int b1 = i1a[r], b2 = i2a[r];
        float G1 = g1a[r], G2 = g2a[r];
        int c = c4 * 4;
        float4 v;
        v.x = (c     == b1) ? G1 : ((c     == b2) ? G2 : 0.0f);
        v.y = (c + 1 == b1) ? G1 : ((c + 1 == b2) ? G2 : 0.0f);
        v.z = (c + 2 == b1) ? G1 : ((c + 2 == b2) ? G2 : 0.0f);
        v.w = (c + 3 == b1) ? G1 : ((c + 3 == b2) ? G2 : 0.0f);
        *(float4*)(out + (size_t)(row0 + r) * EE + c) = v;
    }

    if (write_extras && tid < EE) {
        int cnt = counts[tid];
        if (cnt > 0) atomicAdd(out + ACT_OFF + tid, (float)cnt);
    }
}

extern "C" void kernel_launch(void* const* d_in, const int* in_sizes, int n_in,
                              void* d_out, int out_size) {
    const float* x     = (const float*)d_in[0];
    const float* w     = (const float*)d_in[1];
    const float* noise = (const float*)d_in[2];
    float* out = (float*)d_out;

    const int write_extras = ((size_t)out_size >= FULL_OUT) ? 1 : 0;

    cudaFuncSetAttribute(router_kernel,
                         cudaFuncAttributeMaxDynamicSharedMemorySize, SMEM_BYTES);

    if (write_extras) {
        zero_act_kernel<<<1, 64>>>(out + ACT_OFF);
    }
    router_kernel<<<TT / BM, NTHREADS, SMEM_BYTES>>>(x, w, noise, out, write_extras);
}

// round 3
// speedup vs baseline: 1.4266x; 1.4266x over previous
#include <cuda_runtime.h>
#include <cstdint>

#define TT 16384
#define DD 2048
#define EE 64
#define BM 128
#define BK 32
#define NCHUNK (DD / BK)     // 64
#define NTHREADS 256

// ---- shared memory layout (float offsets) ----
// Per buffer: A_hi[128][36], A_lo[128][36], B_hi[32][72], B_lo[32][72]
#define A_STRIDE 36
#define B_STRIDE 72
#define A_TILE (BM * A_STRIDE)            // 4608
#define B_TILE (BK * B_STRIDE)            // 2304
#define BUF_FLOATS (2 * A_TILE + 2 * B_TILE)   // 13824
#define A_HI_OFF(b) ((b) * BUF_FLOATS)
#define A_LO_OFF(b) ((b) * BUF_FLOATS + A_TILE)
#define B_HI_OFF(b) ((b) * BUF_FLOATS + 2 * A_TILE)
#define B_LO_OFF(b) ((b) * BUF_FLOATS + 2 * A_TILE + B_TILE)
#define AUX   (2 * BUF_FLOATS)            // 27648
#define CNT   (AUX)                       // int[64]
#define I1A   (CNT + 64)
#define I2A   (I1A + 128)
#define G1A   (I2A + 128)
#define G2A   (G1A + 128)
#define SMEM_FLOATS (G2A + 128)
#define SMEM_BYTES (SMEM_FLOATS * 4)      // ~113 KB
#define SC_STRIDE 66                      // even -> aligned float2 stores

// ---- output layout (floats) ----
#define IDX_OFF  ((size_t)TT * EE)
#define GATE_OFF (IDX_OFF + 2 * (size_t)TT)
#define ACT_OFF  (GATE_OFF + 2 * (size_t)TT)
#define FULL_OUT (ACT_OFF + EE)

// w split into tf32 hi/lo (same [K][E] layout as input w: already B[k][n] row-major)
__device__ float g_w_hi[DD * EE];
__device__ float g_w_lo[DD * EE];

__device__ __forceinline__ float tf32_rna(float v) {
    uint32_t r;
    asm("cvt.rna.tf32.f32 %0, %1;" : "=r"(r) : "f"(v));
    return __uint_as_float(r);
}

__device__ __forceinline__ void mma_tf32(float* d, const uint32_t* a, const uint32_t* b) {
    asm volatile(
        "mma.sync.aligned.m16n8k8.row.col.f32.tf32.tf32.f32 "
        "{%0,%1,%2,%3}, {%4,%5,%6,%7}, {%8,%9}, {%0,%1,%2,%3};"
        : "+f"(d[0]), "+f"(d[1]), "+f"(d[2]), "+f"(d[3])
        : "r"(a[0]), "r"(a[1]), "r"(a[2]), "r"(a[3]), "r"(b[0]), "r"(b[1]));
}

// ======================= prep: split w into tf32 hi/lo, zero activation =======================
__global__ void prep_kernel(const float* __restrict__ w, float* __restrict__ out,
                            int write_extras) {
    int t = blockIdx.x * blockDim.x + threadIdx.x;   // 16384 threads
#pragma unroll
    for (int j = 0; j < 2; j++) {
        int f4 = t * 2 + j;                          // 0..32767
        float4 v = ((const float4*)w)[f4];
        float4 h, l;
        h.x = tf32_rna(v.x); l.x = tf32_rna(v.x - h.x);
        h.y = tf32_rna(v.y); l.y = tf32_rna(v.y - h.y);
        h.z = tf32_rna(v.z); l.z = tf32_rna(v.z - h.z);
        h.w = tf32_rna(v.w); l.w = tf32_rna(v.w - h.w);
        ((float4*)g_w_hi)[f4] = h;
        ((float4*)g_w_lo)[f4] = l;
    }
    if (write_extras && blockIdx.x == 0 && threadIdx.x < EE)
        out[ACT_OFF + threadIdx.x] = 0.0f;
}

// ======================= main kernel =======================
__global__ __launch_bounds__(NTHREADS, 1)
void router_mma_kernel(const float* __restrict__ x,
                       const float* __restrict__ noise,
                       float* __restrict__ out,
                       int write_extras) {
    extern __shared__ float sm[];
    const int tid = threadIdx.x;
    const int wid = tid >> 5;
    const int lid = tid & 31;
    const int row0 = blockIdx.x * BM;

    const int wr0 = (wid >> 1) * 32;   // warp's first row (4 row groups)
    const int ch  = wid & 1;           // warp's col half (2 x 32 cols)
    const int l4  = lid >> 2;          // 0..7
    const int lm  = lid & 3;           // 0..3

    // fragment base offsets (floats, within a tile)
    const int aoff0 = (wr0 + l4) * A_STRIDE + lm;     // + mb*576 + ks*8 (+288 for row+8, +4 for col+4)
    const int boff0 = lm * B_STRIDE + ch * 32 + l4;   // + nb*8 + ks*576 (+288 for k+4)

    float acc[2][4][4];
#pragma unroll
    for (int mb = 0; mb < 2; mb++)
#pragma unroll
        for (int nb = 0; nb < 4; nb++)
#pragma unroll
            for (int i = 0; i < 4; i++) acc[mb][nb][i] = 0.0f;

    // ---- preload chunk 0 into smem ----
    {
#pragma unroll
        for (int j = 0; j < 4; j++) {
            int flat = tid + NTHREADS * j;           // 1024 float4 of x tile
            int r = flat >> 3, kc = flat & 7;
            float4 v = *(const float4*)(x + (size_t)(row0 + r) * DD + kc * 4);
            float4 h, l;
            h.x = tf32_rna(v.x); l.x = tf32_rna(v.x - h.x);
            h.y = tf32_rna(v.y); l.y = tf32_rna(v.y - h.y);
            h.z = tf32_rna(v.z); l.z = tf32_rna(v.z - h.z);
            h.w = tf32_rna(v.w); l.w = tf32_rna(v.w - h.w);
            *(float4*)(sm + A_HI_OFF(0) + r * A_STRIDE + kc * 4) = h;
            *(float4*)(sm + A_LO_OFF(0) + r * A_STRIDE + kc * 4) = l;
        }
#pragma unroll
        for (int j = 0; j < 2; j++) {
            int f4 = tid + NTHREADS * j;             // 512 float4 of B tile
            int k = f4 >> 4, e4 = f4 & 15;
            float4 vh = *(const float4*)(g_w_hi + (size_t)k * EE + e4 * 4);
            float4 vl = *(const float4*)(g_w_lo + (size_t)k * EE + e4 * 4);
            *(float4*)(sm + B_HI_OFF(0) + k * B_STRIDE + e4 * 4) = vh;
            *(float4*)(sm + B_LO_OFF(0) + k * B_STRIDE + e4 * 4) = vl;
        }
    }
    __syncthreads();

    int buf = 0;
    for (int chunk = 0; chunk < NCHUNK; ++chunk) {
        const bool more = (chunk + 1 < NCHUNK);
        float4 xr[4], wh[2], wl[2];
        if (more) {
            const int kbase = (chunk + 1) * BK;
#pragma unroll
            for (int j = 0; j < 4; j++) {
                int flat = tid + NTHREADS * j;
                int r = flat >> 3, kc = flat & 7;
                xr[j] = *(const float4*)(x + (size_t)(row0 + r) * DD + kbase + kc * 4);
            }
#pragma unroll
            for (int j = 0; j < 2; j++) {
                int f4 = tid + NTHREADS * j;
                int k = f4 >> 4, e4 = f4 & 15;
                wh[j] = *(const float4*)(g_w_hi + (size_t)(kbase + k) * EE + e4 * 4);
                wl[j] = *(const float4*)(g_w_lo + (size_t)(kbase + k) * EE + e4 * 4);
            }
        }

        // ---- MMA phase on current buffer ----
        const float* Ah = sm + A_HI_OFF(buf);
        const float* Al = sm + A_LO_OFF(buf);
        const float* Bh = sm + B_HI_OFF(buf);
        const float* Bl = sm + B_LO_OFF(buf);
#pragma unroll
        for (int ks = 0; ks < 4; ks++) {
            uint32_t ahi[2][4], alo[2][4], bhi[4][2], blo[4][2];
            const int ak = aoff0 + ks * 8;
#pragma unroll
            for (int mb = 0; mb < 2; mb++) {
                const int o = ak + mb * (16 * A_STRIDE);
                ahi[mb][0] = __float_as_uint(Ah[o]);
                ahi[mb][1] = __float_as_uint(Ah[o + 8 * A_STRIDE]);
                ahi[mb][2] = __float_as_uint(Ah[o + 4]);
                ahi[mb][3] = __float_as_uint(Ah[o + 8 * A_STRIDE + 4]);
                alo[mb][0] = __float_as_uint(Al[o]);
                alo[mb][1] = __float_as_uint(Al[o + 8 * A_STRIDE]);
                alo[mb][2] = __float_as_uint(Al[o + 4]);
                alo[mb][3] = __float_as_uint(Al[o + 8 * A_STRIDE + 4]);
            }
            const int bk = boff0 + ks * (8 * B_STRIDE);
#pragma unroll
            for (int nb = 0; nb < 4; nb++) {
                const int o = bk + nb * 8;
                bhi[nb][0] = __float_as_uint(Bh[o]);
                bhi[nb][1] = __float_as_uint(Bh[o + 4 * B_STRIDE]);
                blo[nb][0] = __float_as_uint(Bl[o]);
                blo[nb][1] = __float_as_uint(Bl[o + 4 * B_STRIDE]);
            }
#pragma unroll
            for (int mb = 0; mb < 2; mb++)
#pragma unroll
                for (int nb = 0; nb < 4; nb++)
                    mma_tf32(acc[mb][nb], ahi[mb], bhi[nb]);
#pragma unroll
            for (int mb = 0; mb < 2; mb++)
#pragma unroll
                for (int nb = 0; nb < 4; nb++)
                    mma_tf32(acc[mb][nb], ahi[mb], blo[nb]);
#pragma unroll
            for (int mb = 0; mb < 2; mb++)
#pragma unroll
                for (int nb = 0; nb < 4; nb++)
                    mma_tf32(acc[mb][nb], alo[mb], bhi[nb]);
        }

        if (more) {
            __syncthreads();
            const int nb2 = buf ^ 1;
#pragma unroll
            for (int j = 0; j < 4; j++) {
                int flat = tid + NTHREADS * j;
                int r = flat >> 3, kc = flat & 7;
                float4 v = xr[j];
                float4 h, l;
                h.x = tf32_rna(v.x); l.x = tf32_rna(v.x - h.x);
                h.y = tf32_rna(v.y); l.y = tf32_rna(v.y - h.y);
                h.z = tf32_rna(v.z); l.z = tf32_rna(v.z - h.z);
                h.w = tf32_rna(v.w); l.w = tf32_rna(v.w - h.w);
                *(float4*)(sm + A_HI_OFF(nb2) + r * A_STRIDE + kc * 4) = h;
                *(float4*)(sm + A_LO_OFF(nb2) + r * A_STRIDE + kc * 4) = l;
            }
#pragma unroll
            for (int j = 0; j < 2; j++) {
                int f4 = tid + NTHREADS * j;
                int k = f4 >> 4, e4 = f4 & 15;
                *(float4*)(sm + B_HI_OFF(nb2) + k * B_STRIDE + e4 * 4) = wh[j];
                *(float4*)(sm + B_LO_OFF(nb2) + k * B_STRIDE + e4 * 4) = wl[j];
            }
            __syncthreads();
            buf = nb2;
        }
    }

    // ================= epilogue =================
    __syncthreads();                      // done reading tiles; reuse smem
    float* sc = sm;                       // [BM][SC_STRIDE]
    int*   counts = (int*)(sm + CNT);
    int*   i1a = (int*)(sm + I1A);
    int*   i2a = (int*)(sm + I2A);
    float* g1a = sm + G1A;
    float* g2a = sm + G2A;

    // scatter accumulators to score board (float2: adjacent cols)
#pragma unroll
    for (int mb = 0; mb < 2; mb++) {
        int rbase = wr0 + mb * 16 + l4;
#pragma unroll
        for (int nb = 0; nb < 4; nb++) {
            int c = ch * 32 + nb * 8 + lm * 2;
            float2 v0; v0.x = acc[mb][nb][0]; v0.y = acc[mb][nb][1];
            float2 v1; v1.x = acc[mb][nb][2]; v1.y = acc[mb][nb][3];
            *(float2*)(sc + rbase * SC_STRIDE + c)       = v0;
            *(float2*)(sc + (rbase + 8) * SC_STRIDE + c) = v1;
        }
    }
    if (tid < EE) counts[tid] = 0;
    __syncthreads();

    // add noise (coalesced global reads)
#pragma unroll
    for (int j = 0; j < 32; j++) {
        int flat = tid + NTHREADS * j;    // 8192 elems
        int r = flat >> 6, e = flat & 63;
        sc[r * SC_STRIDE + e] += noise[(size_t)row0 * EE + flat];
    }
    __syncthreads();

    // per-row top-2 + gates (renormalized top-2 softmax == sigmoid of score diff)
    if (tid < BM) {
        const int row = tid;
        const float* p = sc + row * SC_STRIDE;
        float m1 = -3.402823466e38f, m2 = -3.402823466e38f;
        int b1 = 0, b2 = 0;
#pragma unroll
        for (int e = 0; e < EE; e++) {
            float z = p[e];
            if (z > m1) { m2 = m1; b2 = b1; m1 = z; b1 = e; }
            else if (z > m2) { m2 = z; b2 = e; }
        }
        float e2 = __expf(m2 - m1);
        float inv = 1.0f / (1.0f + e2);
        float g1 = inv, g2 = e2 * inv;
        i1a[row] = b1; i2a[row] = b2; g1a[row] = g1; g2a[row] = g2;
        atomicAdd(&counts[b1], 1);
        atomicAdd(&counts[b2], 1);
        if (write_extras) {
            float2 iv; iv.x = (float)b1; iv.y = (float)b2;
            *(float2*)(out + IDX_OFF + (size_t)(row0 + row) * 2) = iv;
            float2 gv; gv.x = g1; gv.y = g2;
            *(float2*)(out + GATE_OFF + (size_t)(row0 + row) * 2) = gv;
        }
    }
    __syncthreads();

    // combine tensor (float4 coalesced)
#pragma unroll
    for (int j = 0; j < 8; j++) {
        int chunk = tid + NTHREADS * j;   // 2048 float4
        int r = chunk >> 4, c4 = chunk & 15;
        int b1 = i1a[r], b2 = i2a[r];
        float G1 = g1a[r], G2 = g2a[r];
        int c = c4 * 4;
        float4 v;
        v.x = (c     == b1) ? G1 : ((c     == b2) ? G2 : 0.0f);
        v.y = (c + 1 == b1) ? G1 : ((c + 1 == b2) ? G2 : 0.0f);
        v.z = (c + 2 == b1) ? G1 : ((c + 2 == b2) ? G2 : 0.0f);
        v.w = (c + 3 == b1) ? G1 : ((c + 3 == b2) ? G2 : 0.0f);
        *(float4*)(out + (size_t)(row0 + r) * EE + c) = v;
    }

    if (write_extras && tid < EE) {
        int cnt = counts[tid];
        if (cnt > 0) atomicAdd(out + ACT_OFF + tid, (float)cnt);
    }
}

extern "C" void kernel_launch(void* const* d_in, const int* in_sizes, int n_in,
                              void* d_out, int out_size) {
    const float* x     = (const float*)d_in[0];
    const float* w     = (const float*)d_in[1];
    const float* noise = (const float*)d_in[2];
    float* out = (float*)d_out;

    const int write_extras = ((size_t)out_size >= FULL_OUT) ? 1 : 0;

    cudaFuncSetAttribute(router_mma_kernel,
                         cudaFuncAttributeMaxDynamicSharedMemorySize, SMEM_BYTES);

    prep_kernel<<<64, NTHREADS>>>(w, out, write_extras);
    router_mma_kernel<<<TT / BM, NTHREADS, SMEM_BYTES>>>(x, noise, out, write_extras);
}

// round 4
// speedup vs baseline: 2.4358x; 1.7074x over previous
#include <cuda_runtime.h>
#include <cuda_fp16.h>
#include <cstdint>

#define TT 16384
#define DD 2048
#define EE 64
#define BM 128
#define BK 32
#define NT 512
#define NCH 32                 // chunks per K-set (each set covers K=1024)

// ---- smem layout (u32 offsets) ----
#define A_ROW_U32 20           // 128 rows x 20 u32 (16 data + 4 pad) -> conflict-free frag reads
#define A_PLANE (BM * A_ROW_U32)              // 2560
#define SET_U32 14336
#define AOFF(s,b,pl) ((s)*SET_U32 + (b)*5120 + (pl)*A_PLANE)
#define BOFF(s,b)    ((s)*SET_U32 + 10240 + (b)*2048)
#define SMEM_U32 (2 * SET_U32)                // 28672
#define SMEM_BYTES (SMEM_U32 * 4)             // 114688

// epilogue overlay (u32 offsets)
#define SC_STRIDE 66
#define BOARD_U32 (BM * SC_STRIDE)            // 8448
#define CNT (2 * BOARD_U32)                   // 16896
#define I1A (CNT + 64)
#define I2A (I1A + 128)
#define G1A (I2A + 128)
#define G2A (G1A + 128)

// ---- output layout (floats) ----
#define IDX_OFF  ((size_t)TT * EE)
#define GATE_OFF (IDX_OFF + 2 * (size_t)TT)
#define ACT_OFF  (GATE_OFF + 2 * (size_t)TT)
#define FULL_OUT (ACT_OFF + EE)

// w pre-split to fp16 hi/lo, fragment-major: [k16-step 128][nb 8][lane 32] uint4
__device__ uint4 g_w_frag[128 * 8 * 32];

__device__ __forceinline__ uint32_t packh2(__half a, __half b) {
    uint32_t u;
    asm("mov.b32 %0, {%1, %2};" : "=r"(u) : "h"(__half_as_ushort(a)), "h"(__half_as_ushort(b)));
    return u;
}
__device__ __forceinline__ void split_f16(float x, __half& h, __half& l) {
    h = __float2half_rn(x);
    l = __float2half_rn(x - __half2float(h));
}
__device__ __forceinline__ void mma_f16(float* d, const uint32_t* a, uint32_t b0, uint32_t b1) {
    asm volatile(
        "mma.sync.aligned.m16n8k16.row.col.f32.f16.f16.f32 "
        "{%0,%1,%2,%3}, {%4,%5,%6,%7}, {%8,%9}, {%0,%1,%2,%3};"
        : "+f"(d[0]), "+f"(d[1]), "+f"(d[2]), "+f"(d[3])
        : "r"(a[0]), "r"(a[1]), "r"(a[2]), "r"(a[3]), "r"(b0), "r"(b1));
}
#define BARSET(s) asm volatile("bar.sync %0, %1;" :: "r"((s) + 1), "r"(256) : "memory")

// ======================= prep: w -> fragment-major fp16 hi/lo =======================
__global__ void prep_kernel(const float* __restrict__ w, float* __restrict__ out, int we) {
    int t = blockIdx.x * 256 + threadIdx.x;   // 32768 threads
    int ks = t >> 8, rem = t & 255, nb = rem >> 5, l = rem & 31;
    int n = nb * 8 + (l >> 2), tig = l & 3;
    int k0 = ks * 16 + 2 * tig, k1 = k0 + 8;
    float w00 = w[(size_t)k0 * EE + n],       w01 = w[(size_t)(k0 + 1) * EE + n];
    float w10 = w[(size_t)k1 * EE + n],       w11 = w[(size_t)(k1 + 1) * EE + n];
    __half h00, l00, h01, l01, h10, l10, h11, l11;
    split_f16(w00, h00, l00); split_f16(w01, h01, l01);
    split_f16(w10, h10, l10); split_f16(w11, h11, l11);
    uint4 v;
    v.x = packh2(h00, h01);  // b0 hi
    v.y = packh2(h10, h11);  // b1 hi
    v.z = packh2(l00, l01);  // b0 lo
    v.w = packh2(l10, l11);  // b1 lo
    g_w_frag[t] = v;
    if (we && t < EE) out[ACT_OFF + t] = 0.0f;
}

// ======================= main kernel =======================
__global__ __launch_bounds__(NT, 1)
void router_mma_kernel(const float* __restrict__ x,
                       const float* __restrict__ noise,
                       float* __restrict__ out,
                       int write_extras) {
    extern __shared__ uint32_t smu[];
    const int tid = threadIdx.x;
    const int wid = tid >> 5;
    const int lid = tid & 31;
    const int set = tid >> 8;          // K-set: 0 -> k<1024, 1 -> k>=1024
    const int st  = tid & 255;         // thread id within set
    const int ws  = wid & 7;           // warp id within set
    const int row0 = blockIdx.x * BM;

    const int wr0 = (ws >> 1) * 32;    // warp row base (32-row tile)
    const int chf = ws & 1;            // warp col half (32 cols)
    const int g   = lid >> 2;          // groupID
    const int tig = lid & 3;

    float acc[2][4][4];
#pragma unroll
    for (int mb = 0; mb < 2; mb++)
#pragma unroll
        for (int nb = 0; nb < 4; nb++)
#pragma unroll
            for (int i = 0; i < 4; i++) acc[mb][nb][i] = 0.0f;

    const size_t xko = (size_t)set * 1024;   // this set's K offset in x
    const int wfb = set * 64;                // this set's first k16-step in g_w_frag

    // ---- produce chunk 0 ----
    {
        uint32_t* Ah = smu + AOFF(set, 0, 0);
        uint32_t* Al = smu + AOFF(set, 0, 1);
#pragma unroll
        for (int j = 0; j < 4; j++) {
            int flat = st + 256 * j;               // 1024 float4 of x tile
            int r = flat >> 3, kc = flat & 7;
            float4 v = *(const float4*)(x + (size_t)(row0 + r) * DD + xko + kc * 4);
            __half hx, lx, hy, ly, hz, lz, hw, lw;
            split_f16(v.x, hx, lx); split_f16(v.y, hy, ly);
            split_f16(v.z, hz, lz); split_f16(v.w, hw, lw);
            *(uint2*)(Ah + r * A_ROW_U32 + kc * 2) = make_uint2(packh2(hx, hy), packh2(hz, hw));
            *(uint2*)(Al + r * A_ROW_U32 + kc * 2) = make_uint2(packh2(lx, ly), packh2(lz, lw));
        }
        uint4* Bs = (uint4*)(smu + BOFF(set, 0));
        const uint4* Bg = g_w_frag + (size_t)wfb * 256;
#pragma unroll
        for (int j = 0; j < 2; j++) Bs[st + 256 * j] = Bg[st + 256 * j];
    }
    BARSET(set);

    int buf = 0;
    for (int c = 0; c < NCH; ++c) {
        const bool more = (c + 1 < NCH);
        float4 xr[4];
        uint4  br[2];
        if (more) {
            const size_t kb = xko + (size_t)(c + 1) * BK;
#pragma unroll
            for (int j = 0; j < 4; j++) {
                int flat = st + 256 * j;
                int r = flat >> 3, kc = flat & 7;
                xr[j] = *(const float4*)(x + (size_t)(row0 + r) * DD + kb + kc * 4);
            }
            const uint4* Bg = g_w_frag + (size_t)(wfb + (c + 1) * 2) * 256;
#pragma unroll
            for (int j = 0; j < 2; j++) br[j] = Bg[st + 256 * j];
        }

        // ---- MMA on current buffer ----
        const uint32_t* Ah = smu + AOFF(set, buf, 0);
        const uint32_t* Al = smu + AOFF(set, buf, 1);
        const uint4*    Bs = (const uint4*)(smu + BOFF(set, buf));
#pragma unroll
        for (int ks = 0; ks < 2; ks++) {
            const int o = ks * 8 + tig;
            uint32_t ah[2][4], al[2][4];
#pragma unroll
            for (int mb = 0; mb < 2; mb++) {
                const int r = wr0 + mb * 16 + g;
                ah[mb][0] = Ah[r * A_ROW_U32 + o];
                ah[mb][1] = Ah[(r + 8) * A_ROW_U32 + o];
                ah[mb][2] = Ah[r * A_ROW_U32 + o + 4];
                ah[mb][3] = Ah[(r + 8) * A_ROW_U32 + o + 4];
                al[mb][0] = Al[r * A_ROW_U32 + o];
                al[mb][1] = Al[(r + 8) * A_ROW_U32 + o];
                al[mb][2] = Al[r * A_ROW_U32 + o + 4];
                al[mb][3] = Al[(r + 8) * A_ROW_U32 + o + 4];
            }
#pragma unroll
            for (int nb = 0; nb < 4; nb++) {
                uint4 bv = Bs[(ks * 8 + chf * 4 + nb) * 32 + lid];
#pragma unroll
                for (int mb = 0; mb < 2; mb++) {
                    mma_f16(acc[mb][nb], ah[mb], bv.x, bv.y);   // h*h
                    mma_f16(acc[mb][nb], ah[mb], bv.z, bv.w);   // h*l
                    mma_f16(acc[mb][nb], al[mb], bv.x, bv.y);   // l*h
                    mma_f16(acc[mb][nb], al[mb], bv.z, bv.w);   // l*l
                }
            }
        }
        BARSET(set);

        if (more) {
            const int nbuf = buf ^ 1;
            uint32_t* Ahn = smu + AOFF(set, nbuf, 0);
            uint32_t* Aln = smu + AOFF(set, nbuf, 1);
#pragma unroll
            for (int j = 0; j < 4; j++) {
                int flat = st + 256 * j;
                int r = flat >> 3, kc = flat & 7;
                float4 v = xr[j];
                __half hx, lx, hy, ly, hz, lz, hw, lw;
                split_f16(v.x, hx, lx); split_f16(v.y, hy, ly);
                split_f16(v.z, hz, lz); split_f16(v.w, hw, lw);
                *(uint2*)(Ahn + r * A_ROW_U32 + kc * 2) = make_uint2(packh2(hx, hy), packh2(hz, hw));
                *(uint2*)(Aln + r * A_ROW_U32 + kc * 2) = make_uint2(packh2(lx, ly), packh2(lz, lw));
            }
            uint4* Bsn = (uint4*)(smu + BOFF(set, nbuf));
#pragma unroll
            for (int j = 0; j < 2; j++) Bsn[st + 256 * j] = br[j];
            BARSET(set);
            buf = nbuf;
        }
    }

    // ================= epilogue =================
    __syncthreads();                       // both sets done; reuse smem
    float* sc0 = (float*)smu;              // board set 0: [128][66]
    float* sc1 = (float*)(smu + BOARD_U32);
    float* scb = set ? sc1 : sc0;
    int*   counts = (int*)(smu + CNT);
    int*   i1a = (int*)(smu + I1A);
    int*   i2a = (int*)(smu + I2A);
    float* g1a = (float*)(smu + G1A);
    float* g2a = (float*)(smu + G2A);

    // scatter accumulators to this set's board
#pragma unroll
    for (int mb = 0; mb < 2; mb++) {
        int rbase = wr0 + mb * 16 + g;
#pragma unroll
        for (int nb = 0; nb < 4; nb++) {
            int cc = chf * 32 + nb * 8 + tig * 2;
            float2 v0; v0.x = acc[mb][nb][0]; v0.y = acc[mb][nb][1];
            float2 v1; v1.x = acc[mb][nb][2]; v1.y = acc[mb][nb][3];
            *(float2*)(scb + rbase * SC_STRIDE + cc)       = v0;
            *(float2*)(scb + (rbase + 8) * SC_STRIDE + cc) = v1;
        }
    }
    if (tid < EE) counts[tid] = 0;
    __syncthreads();

    // sum K-halves + noise (coalesced)
#pragma unroll
    for (int j = 0; j < 16; j++) {
        int flat = tid + NT * j;           // 8192 elems
        int r = flat >> 6, e = flat & 63;
        sc0[r * SC_STRIDE + e] = sc0[r * SC_STRIDE + e] + sc1[r * SC_STRIDE + e]
                               + noise[(size_t)row0 * EE + flat];
    }
    __syncthreads();

    // per-row top-2 + gates (renormalized top-2 softmax == sigmoid of score diff)
    if (tid < BM) {
        const int row = tid;
        const float* p = sc0 + row * SC_STRIDE;
        float m1 = -3.402823466e38f, m2 = -3.402823466e38f;
        int b1 = 0, b2 = 0;
#pragma unroll
        for (int e = 0; e < EE; e++) {
            float z = p[e];
            if (z > m1) { m2 = m1; b2 = b1; m1 = z; b1 = e; }
            else if (z > m2) { m2 = z; b2 = e; }
        }
        float e2 = __expf(m2 - m1);
        float inv = 1.0f / (1.0f + e2);
        float g1 = inv, g2 = e2 * inv;
        i1a[row] = b1; i2a[row] = b2; g1a[row] = g1; g2a[row] = g2;
        atomicAdd(&counts[b1], 1);
        atomicAdd(&counts[b2], 1);
        if (write_extras) {
            float2 iv; iv.x = (float)b1; iv.y = (float)b2;
            *(float2*)(out + IDX_OFF + (size_t)(row0 + row) * 2) = iv;
            float2 gv; gv.x = g1; gv.y = g2;
            *(float2*)(out + GATE_OFF + (size_t)(row0 + row) * 2) = gv;
        }
    }
    __syncthreads();

    // combine tensor (float4 coalesced)
#pragma unroll
    for (int j = 0; j < 4; j++) {
        int chunk = tid + NT * j;          // 2048 float4
        int r = chunk >> 4, c4 = chunk & 15;
        int b1 = i1a[r], b2 = i2a[r];
        float G1 = g1a[r], G2 = g2a[r];
        int cc = c4 * 4;
        float4 v;
        v.x = (cc     == b1) ? G1 : ((cc     == b2) ? G2 : 0.0f);
        v.y = (cc + 1 == b1) ? G1 : ((cc + 1 == b2) ? G2 : 0.0f);
        v.z = (cc + 2 == b1) ? G1 : ((cc + 2 == b2) ? G2 : 0.0f);
        v.w = (cc + 3 == b1) ? G1 : ((cc + 3 == b2) ? G2 : 0.0f);
        *(float4*)(out + (size_t)(row0 + r) * EE + cc) = v;
    }

    if (write_extras && tid < EE) {
        int cnt = counts[tid];
        if (cnt > 0) atomicAdd(out + ACT_OFF + tid, (float)cnt);
    }
}

extern "C" void kernel_launch(void* const* d_in, const int* in_sizes, int n_in,
                              void* d_out, int out_size) {
    const float* x     = (const float*)d_in[0];
    const float* w     = (const float*)d_in[1];
    const float* noise = (const float*)d_in[2];
    float* out = (float*)d_out;

    const int write_extras = ((size_t)out_size >= FULL_OUT) ? 1 : 0;

    cudaFuncSetAttribute(router_mma_kernel,
                         cudaFuncAttributeMaxDynamicSharedMemorySize, SMEM_BYTES);

    prep_kernel<<<128, 256>>>(w, out, write_extras);
    router_mma_kernel<<<TT / BM, NT, SMEM_BYTES>>>(x, noise, out, write_extras);
}

// round 5
// speedup vs baseline: 2.6419x; 1.0846x over previous
#include <cuda_runtime.h>
#include <cuda_fp16.h>
#include <cstdint>

#define TT 16384
#define DD 2048
#define EE 64
#define BM 128
#define BK 32
#define NT 512
#define NCH 32                 // chunks per K-set (each set covers K=1024)

// ---- smem layout (u32 offsets) ----
#define A_ROW_U32 20           // 128 rows x 20 u32 (16 data + 4 pad) -> conflict-free frag reads
#define A_PLANE (BM * A_ROW_U32)              // 2560
#define SET_U32 14336
#define AOFF(s,b,pl) ((s)*SET_U32 + (b)*5120 + (pl)*A_PLANE)
#define BOFF(s,b)    ((s)*SET_U32 + 10240 + (b)*2048)
#define SMEM_U32 (2 * SET_U32)                // 28672
#define SMEM_BYTES (SMEM_U32 * 4)             // 114688

// epilogue overlay (u32 offsets)
#define SC_STRIDE 66
#define BOARD_U32 (BM * SC_STRIDE)            // 8448
#define CNT (2 * BOARD_U32)
#define I1A (CNT + 64)
#define I2A (I1A + 128)
#define G1A (I2A + 128)
#define G2A (G1A + 128)

// ---- output layout (floats) ----
#define IDX_OFF  ((size_t)TT * EE)
#define GATE_OFF (IDX_OFF + 2 * (size_t)TT)
#define ACT_OFF  (GATE_OFF + 2 * (size_t)TT)
#define FULL_OUT (ACT_OFF + EE)

// w pre-split to fp16 hi/lo, fragment-major: [k16-step 128][nb 8][lane 32] uint4
__device__ uint4 g_w_frag[128 * 8 * 32];

__device__ __forceinline__ uint32_t packh2(__half a, __half b) {
    uint32_t u;
    asm("mov.b32 %0, {%1, %2};" : "=r"(u) : "h"(__half_as_ushort(a)), "h"(__half_as_ushort(b)));
    return u;
}
__device__ __forceinline__ void split_f16(float x, __half& h, __half& l) {
    h = __float2half_rn(x);
    l = __float2half_rn(x - __half2float(h));
}
__device__ __forceinline__ void mma_f16(float* d, const uint32_t* a, uint32_t b0, uint32_t b1) {
    asm volatile(
        "mma.sync.aligned.m16n8k16.row.col.f32.f16.f16.f32 "
        "{%0,%1,%2,%3}, {%4,%5,%6,%7}, {%8,%9}, {%0,%1,%2,%3};"
        : "+f"(d[0]), "+f"(d[1]), "+f"(d[2]), "+f"(d[3])
        : "r"(a[0]), "r"(a[1]), "r"(a[2]), "r"(a[3]), "r"(b0), "r"(b1));
}

// named producer/consumer barriers, 256 threads each (128 arrive + 128 sync)
#define BAR_ARRIVE(id) asm volatile("bar.arrive %0, %1;" :: "r"(id), "r"(256))
#define BAR_SYNC(id)   asm volatile("bar.sync %0, %1;"   :: "r"(id), "r"(256) : "memory")
#define FULL_ID(s,b) (1 + (s) * 4 + (b))
#define FREE_ID(s,b) (3 + (s) * 4 + (b))

// ======================= prep: w -> fragment-major fp16 hi/lo =======================
__global__ void prep_kernel(const float* __restrict__ w, float* __restrict__ out, int we) {
    int t = blockIdx.x * 256 + threadIdx.x;   // 32768 threads
    int ks = t >> 8, rem = t & 255, nb = rem >> 5, l = rem & 31;
    int n = nb * 8 + (l >> 2), tig = l & 3;
    int k0 = ks * 16 + 2 * tig, k1 = k0 + 8;
    float w00 = w[(size_t)k0 * EE + n],       w01 = w[(size_t)(k0 + 1) * EE + n];
    float w10 = w[(size_t)k1 * EE + n],       w11 = w[(size_t)(k1 + 1) * EE + n];
    __half h00, l00, h01, l01, h10, l10, h11, l11;
    split_f16(w00, h00, l00); split_f16(w01, h01, l01);
    split_f16(w10, h10, l10); split_f16(w11, h11, l11);
    uint4 v;
    v.x = packh2(h00, h01);
    v.y = packh2(h10, h11);
    v.z = packh2(l00, l01);
    v.w = packh2(l10, l11);
    g_w_frag[t] = v;
    if (we && t < EE) out[ACT_OFF + t] = 0.0f;
}

// ======================= main kernel =======================
__global__ __launch_bounds__(NT, 1)
void router_mma_kernel(const float* __restrict__ x,
                       const float* __restrict__ noise,
                       float* __restrict__ out,
                       int write_extras) {
    extern __shared__ uint32_t smu[];
    const int tid = threadIdx.x;
    const int wid = tid >> 5;
    const int lid = tid & 31;
    const int set = tid >> 8;          // K-set: 0 -> k<1024, 1 -> k>=1024
    const int ws  = wid & 7;           // warp id within set
    const bool is_consumer = (ws < 4);
    const int row0 = blockIdx.x * BM;

    const int g   = lid >> 2;          // groupID within warp
    const int tig = lid & 3;

    const size_t xko = (size_t)set * 1024;   // this set's K offset in x
    const int wfb = set * 64;                // this set's first k16-step in g_w_frag

    float acc[2][8][4];
#pragma unroll
    for (int mb = 0; mb < 2; mb++)
#pragma unroll
        for (int nb = 0; nb < 8; nb++)
#pragma unroll
            for (int i = 0; i < 4; i++) acc[mb][nb][i] = 0.0f;

    if (!is_consumer) {
        // ================= PRODUCER: warps 4..7 of each set =================
        const int pt = tid & 127;      // 0..127 within producer group
        for (int c = 0; c < NCH; ++c) {
            const int b = c & 1;
            // issue loads first (overlap latency with the free-barrier wait)
            float4 xr[8];
            uint4  br[4];
            const size_t kb = xko + (size_t)c * BK;
#pragma unroll
            for (int j = 0; j < 8; j++) {
                int flat = pt + 128 * j;               // 1024 float4 of x tile
                int r = flat >> 3, kc = flat & 7;
                xr[j] = *(const float4*)(x + (size_t)(row0 + r) * DD + kb + kc * 4);
            }
            const uint4* Bg = g_w_frag + (size_t)(wfb + c * 2) * 256;
#pragma unroll
            for (int j = 0; j < 4; j++) br[j] = Bg[pt + 128 * j];

            if (c >= 2) BAR_SYNC(FREE_ID(set, b));

            uint32_t* Ah = smu + AOFF(set, b, 0);
            uint32_t* Al = smu + AOFF(set, b, 1);
#pragma unroll
            for (int j = 0; j < 8; j++) {
                int flat = pt + 128 * j;
                int r = flat >> 3, kc = flat & 7;
                float4 v = xr[j];
                __half hx, lx, hy, ly, hz, lz, hw, lw;
                split_f16(v.x, hx, lx); split_f16(v.y, hy, ly);
                split_f16(v.z, hz, lz); split_f16(v.w, hw, lw);
                *(uint2*)(Ah + r * A_ROW_U32 + kc * 2) = make_uint2(packh2(hx, hy), packh2(hz, hw));
                *(uint2*)(Al + r * A_ROW_U32 + kc * 2) = make_uint2(packh2(lx, ly), packh2(lz, lw));
            }
            uint4* Bs = (uint4*)(smu + BOFF(set, b));
#pragma unroll
            for (int j = 0; j < 4; j++) Bs[pt + 128 * j] = br[j];

            BAR_ARRIVE(FULL_ID(set, b));
        }
    } else {
        // ================= CONSUMER: warps 0..3 of each set =================
        const int cw = wid & 3;        // consumer warp -> rows cw*32..cw*32+31
        for (int c = 0; c < NCH; ++c) {
            const int b = c & 1;
            BAR_SYNC(FULL_ID(set, b));

            const uint32_t* Ah = smu + AOFF(set, b, 0);
            const uint32_t* Al = smu + AOFF(set, b, 1);
            const uint4*    Bs = (const uint4*)(smu + BOFF(set, b));
#pragma unroll
            for (int ks = 0; ks < 2; ks++) {
                const int o = ks * 8 + tig;
                uint32_t ah[2][4], al[2][4];
#pragma unroll
                for (int mb = 0; mb < 2; mb++) {
                    const int r = cw * 32 + mb * 16 + g;
                    ah[mb][0] = Ah[r * A_ROW_U32 + o];
                    ah[mb][1] = Ah[(r + 8) * A_ROW_U32 + o];
                    ah[mb][2] = Ah[r * A_ROW_U32 + o + 4];
                    ah[mb][3] = Ah[(r + 8) * A_ROW_U32 + o + 4];
                    al[mb][0] = Al[r * A_ROW_U32 + o];
                    al[mb][1] = Al[(r + 8) * A_ROW_U32 + o];
                    al[mb][2] = Al[r * A_ROW_U32 + o + 4];
                    al[mb][3] = Al[(r + 8) * A_ROW_U32 + o + 4];
                }
#pragma unroll
                for (int nb = 0; nb < 8; nb++) {
                    uint4 bv = Bs[(ks * 8 + nb) * 32 + lid];
#pragma unroll
                    for (int mb = 0; mb < 2; mb++) {
                        mma_f16(acc[mb][nb], ah[mb], bv.x, bv.y);   // h*h
                        mma_f16(acc[mb][nb], ah[mb], bv.z, bv.w);   // h*l
                        mma_f16(acc[mb][nb], al[mb], bv.x, bv.y);   // l*h
                    }
                }
            }
            BAR_ARRIVE(FREE_ID(set, b));
        }
    }

    // ================= epilogue =================
    __syncthreads();                       // everyone done; reuse smem
    float* sc0 = (float*)smu;              // board set 0: [128][66]
    float* sc1 = (float*)(smu + BOARD_U32);
    int*   counts = (int*)(smu + CNT);
    int*   i1a = (int*)(smu + I1A);
    int*   i2a = (int*)(smu + I2A);
    float* g1a = (float*)(smu + G1A);
    float* g2a = (float*)(smu + G2A);

    if (is_consumer) {
        const int cw = wid & 3;
        float* scb = set ? sc1 : sc0;
#pragma unroll
        for (int mb = 0; mb < 2; mb++) {
            int rbase = cw * 32 + mb * 16 + g;
#pragma unroll
            for (int nb = 0; nb < 8; nb++) {
                int cc = nb * 8 + tig * 2;
                float2 v0; v0.x = acc[mb][nb][0]; v0.y = acc[mb][nb][1];
                float2 v1; v1.x = acc[mb][nb][2]; v1.y = acc[mb][nb][3];
                *(float2*)(scb + rbase * SC_STRIDE + cc)       = v0;
                *(float2*)(scb + (rbase + 8) * SC_STRIDE + cc) = v1;
            }
        }
    }
    if (tid < EE) counts[tid] = 0;
    __syncthreads();

    // sum K-halves + noise (coalesced)
#pragma unroll
    for (int j = 0; j < 16; j++) {
        int flat = tid + NT * j;           // 8192 elems
        int r = flat >> 6, e = flat & 63;
        sc0[r * SC_STRIDE + e] = sc0[r * SC_STRIDE + e] + sc1[r * SC_STRIDE + e]
                               + noise[(size_t)row0 * EE + flat];
    }
    __syncthreads();

    // per-row top-2 + gates (renormalized top-2 softmax == sigmoid of score diff)
    if (tid < BM) {
        const int row = tid;
        const float* p = sc0 + row * SC_STRIDE;
        float m1 = -3.402823466e38f, m2 = -3.402823466e38f;
        int b1 = 0, b2 = 0;
#pragma unroll
        for (int e = 0; e < EE; e++) {
            float z = p[e];
            if (z > m1) { m2 = m1; b2 = b1; m1 = z; b1 = e; }
            else if (z > m2) { m2 = z; b2 = e; }
        }
        float e2 = __expf(m2 - m1);
        float inv = 1.0f / (1.0f + e2);
        float g1 = inv, g2 = e2 * inv;
        i1a[row] = b1; i2a[row] = b2; g1a[row] = g1; g2a[row] = g2;
        atomicAdd(&counts[b1], 1);
        atomicAdd(&counts[b2], 1);
        if (write_extras) {
            float2 iv; iv.x = (float)b1; iv.y = (float)b2;
            *(float2*)(out + IDX_OFF + (size_t)(row0 + row) * 2) = iv;
            float2 gv; gv.x = g1; gv.y = g2;
            *(float2*)(out + GATE_OFF + (size_t)(row0 + row) * 2) = gv;
        }
    }
    __syncthreads();

    // combine tensor (float4 coalesced)
#pragma unroll
    for (int j = 0; j < 4; j++) {
        int chunk = tid + NT * j;          // 2048 float4
        int r = chunk >> 4, c4 = chunk & 15;
        int b1 = i1a[r], b2 = i2a[r];
        float G1 = g1a[r], G2 = g2a[r];
        int cc = c4 * 4;
        float4 v;
        v.x = (cc     == b1) ? G1 : ((cc     == b2) ? G2 : 0.0f);
        v.y = (cc + 1 == b1) ? G1 : ((cc + 1 == b2) ? G2 : 0.0f);
        v.z = (cc + 2 == b1) ? G1 : ((cc + 2 == b2) ? G2 : 0.0f);
        v.w = (cc + 3 == b1) ? G1 : ((cc + 3 == b2) ? G2 : 0.0f);
        *(float4*)(out + (size_t)(row0 + r) * EE + cc) = v;
    }

    if (write_extras && tid < EE) {
        int cnt = counts[tid];
        if (cnt > 0) atomicAdd(out + ACT_OFF + tid, (float)cnt);
    }
}

extern "C" void kernel_launch(void* const* d_in, const int* in_sizes, int n_in,
                              void* d_out, int out_size) {
    const float* x     = (const float*)d_in[0];
    const float* w     = (const float*)d_in[1];
    const float* noise = (const float*)d_in[2];
    float* out = (float*)d_out;

    const int write_extras = ((size_t)out_size >= FULL_OUT) ? 1 : 0;

    cudaFuncSetAttribute(router_mma_kernel,
                         cudaFuncAttributeMaxDynamicSharedMemorySize, SMEM_BYTES);

    prep_kernel<<<128, 256>>>(w, out, write_extras);
    router_mma_kernel<<<TT / BM, NT, SMEM_BYTES>>>(x, noise, out, write_extras);
}